// round 2
// baseline (speedup 1.0000x reference)
#include <cuda_runtime.h>
#include <cuda_bf16.h>
#include <math.h>

#define Wd 256
#define Hd 256
#define HW 65536

// ---------------- scratch buffers (no allocation allowed) ----------------
__device__ float g_buf_a[216 * HW];
__device__ float g_buf_b[216 * HW];
__device__ float g_off [144 * HW];
__device__ float g_mask[ 72 * HW];
__device__ float g_cat [128 * HW];

// ---------------- generic 3x3 conv, pad=1, stride=1 ----------------
// Block: (32,8) threads. Spatial tile 32x32 (4 rows per thread).
// OCB output channels per block (blockIdx.z selects the group).
template<int CIN, int OCB, bool LRELU>
__global__ __launch_bounds__(256)
void conv3x3_kernel(const float* __restrict__ in, const float* __restrict__ wt,
                    const float* __restrict__ bias, float* __restrict__ out)
{
    __shared__ float sin_[34 * 34];
    __shared__ float sw[OCB * 9];
    const int tx = threadIdx.x, ty = threadIdx.y;
    const int tid = ty * 32 + tx;
    const int w0 = blockIdx.x * 32;
    const int h0 = blockIdx.y * 32;
    const int ocbase = blockIdx.z * OCB;

    float acc[OCB][4];
#pragma unroll
    for (int o = 0; o < OCB; o++)
#pragma unroll
        for (int i = 0; i < 4; i++) acc[o][i] = 0.f;

    for (int cin = 0; cin < CIN; cin++) {
        const float* plane = in + (size_t)cin * HW;
        // load 34x34 input tile (zero-padded at image borders)
        for (int i = tid; i < 34 * 34; i += 256) {
            int r = i / 34, c = i - r * 34;
            int gh = h0 + r - 1, gw = w0 + c - 1;
            float v = 0.f;
            if ((unsigned)gh < Hd && (unsigned)gw < Wd) v = plane[gh * Wd + gw];
            sin_[i] = v;
        }
        // load OCB 3x3 filters for this cin
        for (int i = tid; i < OCB * 9; i += 256) {
            int o = i / 9, k = i - o * 9;
            sw[i] = wt[(((size_t)(ocbase + o)) * CIN + cin) * 9 + k];
        }
        __syncthreads();

        float v[6][3];
#pragma unroll
        for (int r = 0; r < 6; r++)
#pragma unroll
            for (int c = 0; c < 3; c++)
                v[r][c] = sin_[(ty * 4 + r) * 34 + tx + c];

#pragma unroll
        for (int o = 0; o < OCB; o++) {
            float k00 = sw[o*9+0], k01 = sw[o*9+1], k02 = sw[o*9+2];
            float k10 = sw[o*9+3], k11 = sw[o*9+4], k12 = sw[o*9+5];
            float k20 = sw[o*9+6], k21 = sw[o*9+7], k22 = sw[o*9+8];
#pragma unroll
            for (int i = 0; i < 4; i++) {
                acc[o][i] += k00*v[i  ][0] + k01*v[i  ][1] + k02*v[i  ][2]
                           + k10*v[i+1][0] + k11*v[i+1][1] + k12*v[i+1][2]
                           + k20*v[i+2][0] + k21*v[i+2][1] + k22*v[i+2][2];
            }
        }
        __syncthreads();
    }

#pragma unroll
    for (int o = 0; o < OCB; o++) {
        float bv = bias[ocbase + o];
#pragma unroll
        for (int i = 0; i < 4; i++) {
            float r = acc[o][i] + bv;
            if (LRELU) r = (r >= 0.f) ? r : 0.1f * r;
            out[(size_t)(ocbase + o) * HW + (h0 + ty * 4 + i) * Wd + (w0 + tx)] = r;
        }
    }
}

// ---------------- offset/mask transform ----------------
// conv_out: 216 planes. off[c] = 10*tanh(conv_out[c]) + flow[(c even)?1:0], c<144.
// mask[c-144] = sigmoid(conv_out[c]), c>=144.
__global__ void offxform_kernel(const float* __restrict__ conv_out,
                                const float* __restrict__ flow,
                                float* __restrict__ off, float* __restrict__ mask)
{
    int idx = blockIdx.x * 256 + threadIdx.x;
    if (idx >= 216 * HW) return;
    int c = idx >> 16;          // idx / HW
    int hw = idx & (HW - 1);
    float v = conv_out[idx];
    if (c < 144) {
        float f = flow[((c & 1) ^ 1) * HW + hw];
        off[idx] = 10.0f * tanhf(v) + f;
    } else {
        mask[(c - 144) * HW + hw] = 1.0f / (1.0f + expf(-v));
    }
}

// ---------------- modulated deformable conv ----------------
// 64 threads = 64 consecutive pixels in one row. For each of 8 groups:
// stage the 72-deep (Cg=8 x K=9) sampled column in smem, then accumulate
// all 64 output channels against the 64x72 weight slice (broadcast LDS).
__global__ __launch_bounds__(64)
void mdcn_kernel(const float* __restrict__ x, const float* __restrict__ off,
                 const float* __restrict__ mask, const float* __restrict__ wt,
                 const float* __restrict__ bias, float* __restrict__ out)
{
    __shared__ float samp[72 * 64];
    __shared__ float wsm[64 * 72];
    const int tid = threadIdx.x;
    const int h = blockIdx.y;
    const int wcol = blockIdx.x * 64 + tid;
    const int hw = h * Wd + wcol;

    float acc[64];
#pragma unroll
    for (int o = 0; o < 64; o++) acc[o] = 0.f;

    for (int g = 0; g < 8; g++) {
        // ---- sampling phase ----
#pragma unroll
        for (int k = 0; k < 9; k++) {
            int gk = g * 9 + k;
            float offy = off[(gk * 2 + 0) * HW + hw];
            float offx = off[(gk * 2 + 1) * HW + hw];
            float m    = mask[gk * HW + hw];
            float py = (float)h    + (float)(k / 3 - 1) + offy;
            float px = (float)wcol + (float)(k % 3 - 1) + offx;
            float y0f = floorf(py), x0f = floorf(px);
            float ly = py - y0f, lx = px - x0f;
            int y0 = (int)y0f, x0i = (int)x0f;
            int y1 = y0 + 1,  x1 = x0i + 1;
            bool vy0 = (unsigned)y0 < Hd, vy1 = (unsigned)y1 < Hd;
            bool vx0 = (unsigned)x0i < Wd, vx1 = (unsigned)x1 < Wd;
            int yc0 = min(max(y0, 0), Hd - 1), yc1 = min(max(y1, 0), Hd - 1);
            int xc0 = min(max(x0i, 0), Wd - 1), xc1 = min(max(x1, 0), Wd - 1);
            float w00 = (vy0 && vx0) ? (1.f - ly) * (1.f - lx) * m : 0.f;
            float w01 = (vy0 && vx1) ? (1.f - ly) * lx * m : 0.f;
            float w10 = (vy1 && vx0) ? ly * (1.f - lx) * m : 0.f;
            float w11 = (vy1 && vx1) ? ly * lx * m : 0.f;
            int i00 = yc0 * Wd + xc0, i01 = yc0 * Wd + xc1;
            int i10 = yc1 * Wd + xc0, i11 = yc1 * Wd + xc1;
#pragma unroll
            for (int c = 0; c < 8; c++) {
                const float* p = x + (size_t)(g * 8 + c) * HW;
                samp[(c * 9 + k) * 64 + tid] =
                    w00 * p[i00] + w01 * p[i01] + w10 * p[i10] + w11 * p[i11];
            }
        }
        // ---- weight slice for this group ----
        for (int i = tid; i < 64 * 72; i += 64) {
            int o = i / 72, ck = i - o * 72;
            int c = ck / 9, k = ck - c * 9;
            wsm[i] = wt[((size_t)o * 64 + g * 8 + c) * 9 + k];
        }
        __syncthreads();
        // ---- accumulate: acc[o] += W[o, g, c, k] * samp[c, k] ----
#pragma unroll 4
        for (int ck = 0; ck < 72; ck++) {
            float s = samp[ck * 64 + tid];
#pragma unroll
            for (int o = 0; o < 64; o++)
                acc[o] += wsm[o * 72 + ck] * s;
        }
        __syncthreads();
    }
#pragma unroll
    for (int o = 0; o < 64; o++)
        out[(size_t)o * HW + hw] = acc[o] + bias[o];
}

// ---------------- host orchestration ----------------
extern "C" void kernel_launch(void* const* d_in, const int* in_sizes, int n_in,
                              void* d_out, int out_size)
{
    const float* feat_prev       = (const float*)d_in[0];
    const float* feat_next       = (const float*)d_in[1];
    const float* extra_feat_prev = (const float*)d_in[2];
    const float* extra_feat_next = (const float*)d_in[3];
    const float* flow_prev       = (const float*)d_in[4];
    const float* flow_next       = (const float*)d_in[5];
    // off1: 6..13, off2: 14..21
    const float* off1_w[4] = {(const float*)d_in[6],  (const float*)d_in[8],
                              (const float*)d_in[10], (const float*)d_in[12]};
    const float* off1_b[4] = {(const float*)d_in[7],  (const float*)d_in[9],
                              (const float*)d_in[11], (const float*)d_in[13]};
    const float* off2_w[4] = {(const float*)d_in[14], (const float*)d_in[16],
                              (const float*)d_in[18], (const float*)d_in[20]};
    const float* off2_b[4] = {(const float*)d_in[15], (const float*)d_in[17],
                              (const float*)d_in[19], (const float*)d_in[21]};
    const float* dcn1_w = (const float*)d_in[22];
    const float* dcn1_b = (const float*)d_in[23];
    const float* dcn2_w = (const float*)d_in[24];
    const float* dcn2_b = (const float*)d_in[25];
    const float* fus_w  = (const float*)d_in[26];
    const float* fus_b  = (const float*)d_in[27];
    float* out = (float*)d_out;

    float *buf_a, *buf_b, *offp, *maskp, *catp;
    cudaGetSymbolAddress((void**)&buf_a, g_buf_a);
    cudaGetSymbolAddress((void**)&buf_b, g_buf_b);
    cudaGetSymbolAddress((void**)&offp,  g_off);
    cudaGetSymbolAddress((void**)&maskp, g_mask);
    cudaGetSymbolAddress((void**)&catp,  g_cat);

    dim3 cb(32, 8);
    dim3 cg64(8, 8, 4);    // 64 output channels, OCB=16
    dim3 cg216(8, 8, 27);  // 216 output channels, OCB=8
    dim3 mg(4, 256);       // mdcn: 4 x 64 pixels per row, 256 rows
    int nxf = (216 * HW + 255) / 256;

    // ---- branch prev ----
    conv3x3_kernel<128, 16, true ><<<cg64,  cb>>>(extra_feat_prev, off1_w[0], off1_b[0], buf_a);
    conv3x3_kernel< 64, 16, true ><<<cg64,  cb>>>(buf_a, off1_w[1], off1_b[1], buf_b);
    conv3x3_kernel< 64, 16, true ><<<cg64,  cb>>>(buf_b, off1_w[2], off1_b[2], buf_a);
    conv3x3_kernel< 64,  8, false><<<cg216, cb>>>(buf_a, off1_w[3], off1_b[3], buf_b);
    offxform_kernel<<<nxf, 256>>>(buf_b, flow_prev, offp, maskp);
    mdcn_kernel<<<mg, 64>>>(feat_prev, offp, maskp, dcn1_w, dcn1_b, catp);

    // ---- branch next ----
    conv3x3_kernel<128, 16, true ><<<cg64,  cb>>>(extra_feat_next, off2_w[0], off2_b[0], buf_a);
    conv3x3_kernel< 64, 16, true ><<<cg64,  cb>>>(buf_a, off2_w[1], off2_b[1], buf_b);
    conv3x3_kernel< 64, 16, true ><<<cg64,  cb>>>(buf_b, off2_w[2], off2_b[2], buf_a);
    conv3x3_kernel< 64,  8, false><<<cg216, cb>>>(buf_a, off2_w[3], off2_b[3], buf_b);
    offxform_kernel<<<nxf, 256>>>(buf_b, flow_next, offp, maskp);
    mdcn_kernel<<<mg, 64>>>(feat_next, offp, maskp, dcn2_w, dcn2_b, catp + (size_t)64 * HW);

    // ---- fusion conv ----
    conv3x3_kernel<128, 16, false><<<cg64, cb>>>(catp, fus_w, fus_b, out);
}